// round 5
// baseline (speedup 1.0000x reference)
#include <cuda_runtime.h>

// B = 65536 point clouds, N = 128 points, 3 coords.
// loss = mean( (xc @ R - yc)^2 )  with  R = U @ Vh  (SVD of C = xc^T yc)
//      = [ sum_b ( ||xc_b||^2 + ||yc_b||^2 - 2*nuclear_norm(C_b) ) ] / (B*N*3)
// nuclear_norm(C) = sum sqrt(eig(C^T C))  via closed-form 3x3 symmetric eigensolver.
//
// R5: revert R4's smem bounce (it ADDED L1 pressure). R3 structure, but
// 2 batches per warp with all 12 LDG.128 issued up front: 2x MLP, 2x
// per-block overhead amortization, contiguous 3KB/warp read per tensor.

#define NB 65536
#define NPTS 128
#define WARPS_PER_BLOCK 8
#define THREADS (WARPS_PER_BLOCK * 32)
#define BATCHES_PER_BLOCK (WARPS_PER_BLOCK * 2)     // 16
#define GRID (NB / BATCHES_PER_BLOCK)               // 4096

__device__ double g_accum = 0.0;
__device__ unsigned int g_count = 0u;

__global__ void __launch_bounds__(THREADS)
kabsch_fused(const float* __restrict__ x, const float* __restrict__ y,
             float* __restrict__ out) {
    const int tid  = threadIdx.x;
    const int lane = tid & 31;
    const int wib  = tid >> 5;

    // Two adjacent batches per warp: 192 contiguous float4 per tensor.
    const size_t pair = (size_t)blockIdx.x * BATCHES_PER_BLOCK + wib * 2;
    const float4* xb = reinterpret_cast<const float4*>(x) + pair * 96;
    const float4* yb = reinterpret_cast<const float4*>(y) + pair * 96;

    // Issue all 12 loads up front (12 outstanding LDG.128 per thread).
    float4 a0 = xb[3 * lane + 0];
    float4 a1 = xb[3 * lane + 1];
    float4 a2 = xb[3 * lane + 2];
    float4 a3 = xb[96 + 3 * lane + 0];
    float4 a4 = xb[96 + 3 * lane + 1];
    float4 a5 = xb[96 + 3 * lane + 2];
    float4 b0 = yb[3 * lane + 0];
    float4 b1 = yb[3 * lane + 1];
    float4 b2 = yb[3 * lane + 2];
    float4 b3 = yb[96 + 3 * lane + 0];
    float4 b4 = yb[96 + 3 * lane + 1];
    float4 b5 = yb[96 + 3 * lane + 2];

    // Reduction rows: red[batch_in_block][acc][lane], row stride 36 floats
    // (16B-aligned, conflict-free). 16*17*36*4B = 39168B.
    __shared__ __align__(16) float red[BATCHES_PER_BLOCK][17][36];
    __shared__ __align__(16) float bsum[BATCHES_PER_BLOCK][20];

    // ---- accumulate batch A ----
    {
        float px[4][3] = {{a0.x, a0.y, a0.z}, {a0.w, a1.x, a1.y},
                          {a1.z, a1.w, a2.x}, {a2.y, a2.z, a2.w}};
        float py[4][3] = {{b0.x, b0.y, b0.z}, {b0.w, b1.x, b1.y},
                          {b1.z, b1.w, b2.x}, {b2.y, b2.z, b2.w}};
        float acc[17];
#pragma unroll
        for (int i = 0; i < 17; i++) acc[i] = 0.0f;
#pragma unroll
        for (int p = 0; p < 4; p++) {
#pragma unroll
            for (int j = 0; j < 3; j++) {
                acc[j]     += px[p][j];
                acc[3 + j] += py[p][j];
                acc[6]     += px[p][j] * px[p][j];
                acc[7]     += py[p][j] * py[p][j];
            }
#pragma unroll
            for (int j = 0; j < 3; j++)
#pragma unroll
                for (int k = 0; k < 3; k++)
                    acc[8 + 3 * j + k] += px[p][j] * py[p][k];
        }
#pragma unroll
        for (int j = 0; j < 17; j++)
            red[wib * 2][j][lane] = acc[j];
    }

    // ---- accumulate batch B ----
    {
        float px[4][3] = {{a3.x, a3.y, a3.z}, {a3.w, a4.x, a4.y},
                          {a4.z, a4.w, a5.x}, {a5.y, a5.z, a5.w}};
        float py[4][3] = {{b3.x, b3.y, b3.z}, {b3.w, b4.x, b4.y},
                          {b4.z, b4.w, b5.x}, {b5.y, b5.z, b5.w}};
        float acc[17];
#pragma unroll
        for (int i = 0; i < 17; i++) acc[i] = 0.0f;
#pragma unroll
        for (int p = 0; p < 4; p++) {
#pragma unroll
            for (int j = 0; j < 3; j++) {
                acc[j]     += px[p][j];
                acc[3 + j] += py[p][j];
                acc[6]     += px[p][j] * px[p][j];
                acc[7]     += py[p][j] * py[p][j];
            }
#pragma unroll
            for (int j = 0; j < 3; j++)
#pragma unroll
                for (int k = 0; k < 3; k++)
                    acc[8 + 3 * j + k] += px[p][j] * py[p][k];
        }
#pragma unroll
        for (int j = 0; j < 17; j++)
            red[wib * 2 + 1][j][lane] = acc[j];
    }

    __syncwarp();

    // ---- per-warp transpose-reduce: lanes 0..16 sum both batches' rows ----
    if (lane < 17) {
#pragma unroll
        for (int bsel = 0; bsel < 2; bsel++) {
            const float4* row =
                reinterpret_cast<const float4*>(&red[wib * 2 + bsel][lane][0]);
            float4 v0 = row[0], v1 = row[1], v2 = row[2], v3 = row[3];
            float4 v4 = row[4], v5 = row[5], v6 = row[6], v7 = row[7];
            float s = (((v0.x + v0.y) + (v0.z + v0.w)) + ((v1.x + v1.y) + (v1.z + v1.w)))
                    + (((v2.x + v2.y) + (v2.z + v2.w)) + ((v3.x + v3.y) + (v3.z + v3.w)))
                    + (((v4.x + v4.y) + (v4.z + v4.w)) + ((v5.x + v5.y) + (v5.z + v5.w)))
                    + (((v6.x + v6.y) + (v6.z + v6.w)) + ((v7.x + v7.y) + (v7.z + v7.w)));
            bsum[wib * 2 + bsel][lane] = s;
        }
    }
    __syncthreads();

    // ---- epilogue: lanes 0..15 of warp 0 each finalize one batch ----
    if (tid < 16) {
        const int b = tid;
        const float4* bp = reinterpret_cast<const float4*>(&bsum[b][0]);
        float4 q0 = bp[0], q1 = bp[1], q2 = bp[2], q3 = bp[3];
        float c22 = bsum[b][16];

        float sx0 = q0.x, sx1 = q0.y, sx2 = q0.z;
        float sy0 = q0.w, sy1 = q1.x, sy2 = q1.y;
        float sxx = q1.z, syy = q1.w;
        float C00 = q2.x, C01 = q2.y, C02 = q2.z;
        float C10 = q2.w, C11 = q3.x, C12 = q3.y;
        float C20 = q3.z, C21 = q3.w, C22 = c22;

        const float invN = 1.0f / (float)NPTS;

        float cc00 = C00 - sx0 * sy0 * invN;
        float cc01 = C01 - sx0 * sy1 * invN;
        float cc02 = C02 - sx0 * sy2 * invN;
        float cc10 = C10 - sx1 * sy0 * invN;
        float cc11 = C11 - sx1 * sy1 * invN;
        float cc12 = C12 - sx1 * sy2 * invN;
        float cc20 = C20 - sx2 * sy0 * invN;
        float cc21 = C21 - sx2 * sy1 * invN;
        float cc22 = C22 - sx2 * sy2 * invN;

        float ax = sxx - (sx0 * sx0 + sx1 * sx1 + sx2 * sx2) * invN;
        float ay = syy - (sy0 * sy0 + sy1 * sy1 + sy2 * sy2) * invN;

        // M = C^T C (symmetric PSD)
        float m00 = cc00 * cc00 + cc10 * cc10 + cc20 * cc20;
        float m11 = cc01 * cc01 + cc11 * cc11 + cc21 * cc21;
        float m22 = cc02 * cc02 + cc12 * cc12 + cc22 * cc22;
        float m01 = cc00 * cc01 + cc10 * cc11 + cc20 * cc21;
        float m02 = cc00 * cc02 + cc10 * cc12 + cc20 * cc22;
        float m12 = cc01 * cc02 + cc11 * cc12 + cc21 * cc22;

        // Closed-form eigenvalues (Smith's trig method)
        float q  = (m00 + m11 + m22) * (1.0f / 3.0f);
        float p1 = m01 * m01 + m02 * m02 + m12 * m12;
        float d0 = m00 - q, d1 = m11 - q, d2 = m22 - q;
        float p2 = d0 * d0 + d1 * d1 + d2 * d2 + 2.0f * p1;
        float p  = sqrtf(fmaxf(p2, 0.0f) * (1.0f / 6.0f));

        float nuclear;
        if (p < 1e-10f) {
            nuclear = 3.0f * sqrtf(fmaxf(q, 0.0f));
        } else {
            float ip  = 1.0f / p;
            float b00 = d0 * ip, b11 = d1 * ip, b22 = d2 * ip;
            float b01 = m01 * ip, b02 = m02 * ip, b12 = m12 * ip;
            float detB = b00 * (b11 * b22 - b12 * b12)
                       - b01 * (b01 * b22 - b12 * b02)
                       + b02 * (b01 * b12 - b11 * b02);
            float r = 0.5f * detB;
            r = fminf(1.0f, fmaxf(-1.0f, r));
            float phi = acosf(r) * (1.0f / 3.0f);
            float e1 = q + 2.0f * p * cosf(phi);
            float e3 = q + 2.0f * p * cosf(phi + 2.09439510239319549f); // +2pi/3
            float e2 = 3.0f * q - e1 - e3;
            nuclear = sqrtf(fmaxf(e1, 0.0f))
                    + sqrtf(fmaxf(e2, 0.0f))
                    + sqrtf(fmaxf(e3, 0.0f));
        }

        float loss = ax + ay - 2.0f * nuclear;

        // Sum the 16 per-batch losses (lanes 0..15 active).
        loss += __shfl_xor_sync(0xFFFFu, loss, 8);
        loss += __shfl_xor_sync(0xFFFFu, loss, 4);
        loss += __shfl_xor_sync(0xFFFFu, loss, 2);
        loss += __shfl_xor_sync(0xFFFFu, loss, 1);

        if (tid == 0) {
            atomicAdd(&g_accum, (double)loss);

            // Last-block finalize: counter wraps at GRID-1, so g_count and
            // g_accum are clean for the next graph replay.
            __threadfence();
            unsigned int prev = atomicInc(&g_count, GRID - 1u);
            if (prev == GRID - 1u) {
                double total = atomicAdd(&g_accum, 0.0);  // coherent read
                const double scale = 1.0 / ((double)NB * (double)NPTS * 3.0);
                out[0] = (float)(total * scale);
                g_accum = 0.0;                            // reset for replay
            }
        }
    }
}

extern "C" void kernel_launch(void* const* d_in, const int* in_sizes, int n_in,
                              void* d_out, int out_size) {
    const float* x = (const float*)d_in[0];
    const float* y = (const float*)d_in[1];
    float* out = (float*)d_out;

    kabsch_fused<<<GRID, THREADS>>>(x, y, out);
}

// round 6
// speedup vs baseline: 1.0389x; 1.0389x over previous
#include <cuda_runtime.h>
#include <cstdint>

// B = 65536 point clouds, N = 128 points, 3 coords.
// loss = mean( (xc @ R - yc)^2 )  with  R = U @ Vh  (SVD of C = xc^T yc)
//      = [ sum_b ( ||xc_b||^2 + ||yc_b||^2 - 2*nuclear_norm(C_b) ) ] / (B*N*3)
//
// R6: the 48B/lane LDG pattern has a 3x L1tex wavefront overcount (72 wf/warp
// for 24 unique lines) that saturates L1tex issue. Fix: cp.async.bulk (TMA
// engine) streams GMEM->SMEM with no warp wavefronts; warps re-read via
// conflict-free LDS.128. Compute/reduction identical to the best (R3) kernel.

#define NB 65536
#define NPTS 128
#define WARPS_PER_BLOCK 8
#define THREADS (WARPS_PER_BLOCK * 32)
#define GRID (NB / WARPS_PER_BLOCK)
#define FLOATS_PER_TENSOR (WARPS_PER_BLOCK * 384)   // 3072 floats = 12288 B
#define BYTES_PER_TENSOR (FLOATS_PER_TENSOR * 4)    // 12288
#define BYTES_TOTAL (2 * BYTES_PER_TENSOR)          // 24576

__device__ double g_accum = 0.0;
__device__ unsigned int g_count = 0u;

__device__ __forceinline__ uint32_t smem_u32(const void* p) {
    uint32_t a;
    asm("{ .reg .u64 t; cvta.to.shared.u64 t, %1; cvt.u32.u64 %0, t; }"
        : "=r"(a) : "l"(p));
    return a;
}

__global__ void __launch_bounds__(THREADS)
kabsch_fused(const float* __restrict__ x, const float* __restrict__ y,
             float* __restrict__ out) {
    const int tid  = threadIdx.x;
    const int lane = tid & 31;
    const int wib  = tid >> 5;

    // Staging buffer for the block's 8 batches; reused as reduction array
    // after all warps have consumed their data (union keeps smem ~25KB).
    __shared__ __align__(128) union SmemU {
        struct { float x[FLOATS_PER_TENSOR]; float y[FLOATS_PER_TENSOR]; } d;
        float red[WARPS_PER_BLOCK][17][36];   // 4896 floats < 6144
    } sm;
    __shared__ __align__(16) float bsum[WARPS_PER_BLOCK][20];
    __shared__ __align__(8) uint64_t mbar;

    const uint32_t mb = smem_u32(&mbar);

    if (tid == 0) {
        asm volatile("mbarrier.init.shared::cta.b64 [%0], 1;" :: "r"(mb));
        asm volatile("fence.proxy.async.shared::cta;" ::: "memory");
    }
    __syncthreads();

    if (tid == 0) {
        const float* gx = x + (size_t)blockIdx.x * FLOATS_PER_TENSOR;
        const float* gy = y + (size_t)blockIdx.x * FLOATS_PER_TENSOR;
        asm volatile(
            "mbarrier.arrive.expect_tx.shared::cta.b64 _, [%0], %1;"
            :: "r"(mb), "r"((uint32_t)BYTES_TOTAL) : "memory");
        asm volatile(
            "cp.async.bulk.shared::cta.global.mbarrier::complete_tx::bytes "
            "[%0], [%1], %2, [%3];"
            :: "r"(smem_u32(sm.d.x)), "l"(gx), "r"((uint32_t)BYTES_PER_TENSOR),
               "r"(mb) : "memory");
        asm volatile(
            "cp.async.bulk.shared::cta.global.mbarrier::complete_tx::bytes "
            "[%0], [%1], %2, [%3];"
            :: "r"(smem_u32(sm.d.y)), "l"(gy), "r"((uint32_t)BYTES_PER_TENSOR),
               "r"(mb) : "memory");
    }

    // All threads wait for the bulk copies (phase 0 of a fresh mbarrier).
    {
        uint32_t done = 0;
        while (!done) {
            asm volatile(
                "{\n\t.reg .pred p;\n\t"
                "mbarrier.try_wait.parity.acquire.cta.shared::cta.b64 p, [%1], 0;\n\t"
                "selp.b32 %0, 1, 0, p;\n\t}"
                : "=r"(done) : "r"(mb) : "memory");
        }
    }

    // ---- each warp reads its batch: 48B/lane, conflict-free LDS.128 ----
    const float4* xs = reinterpret_cast<const float4*>(sm.d.x) + wib * 96;
    const float4* ys = reinterpret_cast<const float4*>(sm.d.y) + wib * 96;

    float4 a0 = xs[3 * lane + 0];
    float4 a1 = xs[3 * lane + 1];
    float4 a2 = xs[3 * lane + 2];
    float4 b0 = ys[3 * lane + 0];
    float4 b1 = ys[3 * lane + 1];
    float4 b2 = ys[3 * lane + 2];

    float px[4][3] = {{a0.x, a0.y, a0.z}, {a0.w, a1.x, a1.y},
                      {a1.z, a1.w, a2.x}, {a2.y, a2.z, a2.w}};
    float py[4][3] = {{b0.x, b0.y, b0.z}, {b0.w, b1.x, b1.y},
                      {b1.z, b1.w, b2.x}, {b2.y, b2.z, b2.w}};

    // acc layout: [0..2]=sx, [3..5]=sy, [6]=sxx, [7]=syy, [8..16]=C row-major
    float acc[17];
#pragma unroll
    for (int i = 0; i < 17; i++) acc[i] = 0.0f;

#pragma unroll
    for (int p = 0; p < 4; p++) {
#pragma unroll
        for (int j = 0; j < 3; j++) {
            acc[j]     += px[p][j];
            acc[3 + j] += py[p][j];
            acc[6]     += px[p][j] * px[p][j];
            acc[7]     += py[p][j] * py[p][j];
        }
#pragma unroll
        for (int j = 0; j < 3; j++)
#pragma unroll
            for (int k = 0; k < 3; k++)
                acc[8 + 3 * j + k] += px[p][j] * py[p][k];
    }

    // All warps done reading staging data; reuse it as the reduction array.
    __syncthreads();

#pragma unroll
    for (int j = 0; j < 17; j++)
        sm.red[wib][j][lane] = acc[j];
    __syncwarp();

    if (lane < 17) {
        const float4* row = reinterpret_cast<const float4*>(&sm.red[wib][lane][0]);
        float4 v0 = row[0], v1 = row[1], v2 = row[2], v3 = row[3];
        float4 v4 = row[4], v5 = row[5], v6 = row[6], v7 = row[7];
        float s = (((v0.x + v0.y) + (v0.z + v0.w)) + ((v1.x + v1.y) + (v1.z + v1.w)))
                + (((v2.x + v2.y) + (v2.z + v2.w)) + ((v3.x + v3.y) + (v3.z + v3.w)))
                + (((v4.x + v4.y) + (v4.z + v4.w)) + ((v5.x + v5.y) + (v5.z + v5.w)))
                + (((v6.x + v6.y) + (v6.z + v6.w)) + ((v7.x + v7.y) + (v7.z + v7.w)));
        bsum[wib][lane] = s;
    }
    __syncthreads();

    // ---- epilogue: lanes 0..7 of warp 0 each finalize one batch ----
    if (tid < 8) {
        const int b = tid;
        const float4* bp = reinterpret_cast<const float4*>(&bsum[b][0]);
        float4 q0 = bp[0], q1 = bp[1], q2 = bp[2], q3 = bp[3];
        float c22 = bsum[b][16];

        float sx0 = q0.x, sx1 = q0.y, sx2 = q0.z;
        float sy0 = q0.w, sy1 = q1.x, sy2 = q1.y;
        float sxx = q1.z, syy = q1.w;
        float C00 = q2.x, C01 = q2.y, C02 = q2.z;
        float C10 = q2.w, C11 = q3.x, C12 = q3.y;
        float C20 = q3.z, C21 = q3.w, C22 = c22;

        const float invN = 1.0f / (float)NPTS;

        float cc00 = C00 - sx0 * sy0 * invN;
        float cc01 = C01 - sx0 * sy1 * invN;
        float cc02 = C02 - sx0 * sy2 * invN;
        float cc10 = C10 - sx1 * sy0 * invN;
        float cc11 = C11 - sx1 * sy1 * invN;
        float cc12 = C12 - sx1 * sy2 * invN;
        float cc20 = C20 - sx2 * sy0 * invN;
        float cc21 = C21 - sx2 * sy1 * invN;
        float cc22 = C22 - sx2 * sy2 * invN;

        float ax = sxx - (sx0 * sx0 + sx1 * sx1 + sx2 * sx2) * invN;
        float ay = syy - (sy0 * sy0 + sy1 * sy1 + sy2 * sy2) * invN;

        // M = C^T C (symmetric PSD)
        float m00 = cc00 * cc00 + cc10 * cc10 + cc20 * cc20;
        float m11 = cc01 * cc01 + cc11 * cc11 + cc21 * cc21;
        float m22 = cc02 * cc02 + cc12 * cc12 + cc22 * cc22;
        float m01 = cc00 * cc01 + cc10 * cc11 + cc20 * cc21;
        float m02 = cc00 * cc02 + cc10 * cc12 + cc20 * cc22;
        float m12 = cc01 * cc02 + cc11 * cc12 + cc21 * cc22;

        // Closed-form eigenvalues (Smith's trig method)
        float q  = (m00 + m11 + m22) * (1.0f / 3.0f);
        float p1 = m01 * m01 + m02 * m02 + m12 * m12;
        float d0 = m00 - q, d1 = m11 - q, d2 = m22 - q;
        float p2 = d0 * d0 + d1 * d1 + d2 * d2 + 2.0f * p1;
        float p  = sqrtf(fmaxf(p2, 0.0f) * (1.0f / 6.0f));

        float nuclear;
        if (p < 1e-10f) {
            nuclear = 3.0f * sqrtf(fmaxf(q, 0.0f));
        } else {
            float ip  = 1.0f / p;
            float b00 = d0 * ip, b11 = d1 * ip, b22 = d2 * ip;
            float b01 = m01 * ip, b02 = m02 * ip, b12 = m12 * ip;
            float detB = b00 * (b11 * b22 - b12 * b12)
                       - b01 * (b01 * b22 - b12 * b02)
                       + b02 * (b01 * b12 - b11 * b02);
            float r = 0.5f * detB;
            r = fminf(1.0f, fmaxf(-1.0f, r));
            float phi = acosf(r) * (1.0f / 3.0f);
            float e1 = q + 2.0f * p * cosf(phi);
            float e3 = q + 2.0f * p * cosf(phi + 2.09439510239319549f); // +2pi/3
            float e2 = 3.0f * q - e1 - e3;
            nuclear = sqrtf(fmaxf(e1, 0.0f))
                    + sqrtf(fmaxf(e2, 0.0f))
                    + sqrtf(fmaxf(e3, 0.0f));
        }

        float loss = ax + ay - 2.0f * nuclear;

        loss += __shfl_xor_sync(0xFFu, loss, 4);
        loss += __shfl_xor_sync(0xFFu, loss, 2);
        loss += __shfl_xor_sync(0xFFu, loss, 1);

        if (tid == 0) {
            atomicAdd(&g_accum, (double)loss);

            // Last-block finalize: counter wraps at GRID-1, so g_count and
            // g_accum are clean for the next graph replay.
            __threadfence();
            unsigned int prev = atomicInc(&g_count, GRID - 1u);
            if (prev == GRID - 1u) {
                double total = atomicAdd(&g_accum, 0.0);  // coherent read
                const double scale = 1.0 / ((double)NB * (double)NPTS * 3.0);
                out[0] = (float)(total * scale);
                g_accum = 0.0;                            // reset for replay
            }
        }
    }
}

extern "C" void kernel_launch(void* const* d_in, const int* in_sizes, int n_in,
                              void* d_out, int out_size) {
    const float* x = (const float*)d_in[0];
    const float* y = (const float*)d_in[1];
    float* out = (float*)d_out;

    kabsch_fused<<<GRID, THREADS>>>(x, y, out);
}

// round 7
// speedup vs baseline: 1.3303x; 1.2805x over previous
#include <cuda_runtime.h>

// B = 65536 point clouds, N = 128 points, 3 coords.
// loss = mean( (xc @ R - yc)^2 )  with  R = U @ Vh  (SVD of C = xc^T yc)
//      = [ sum_b ( ||xc_b||^2 + ||yc_b||^2 - 2*nuclear_norm(C_b) ) ] / (B*N*3)
//
// R7: persistent CTAs (888 blocks, grid-stride over 8192 batch-groups).
// Eliminates ~9 wave transitions + 8192 block tails + 8192 global atomics
// that kept R3 off the HBM floor. Per-iteration body identical to R3, with
// bsum double-buffered so only ONE __syncthreads per iteration and the
// warp-0 epilogue overlaps the other warps' next-iteration loads.

#define NB 65536
#define NPTS 128
#define WARPS_PER_BLOCK 8
#define THREADS (WARPS_PER_BLOCK * 32)
#define NGROUPS (NB / WARPS_PER_BLOCK)     // 8192 groups of 8 batches
#define GRID_P 888                          // ~6 resident blocks per SM

__device__ double g_accum = 0.0;
__device__ unsigned int g_count = 0u;

__global__ void __launch_bounds__(THREADS)
kabsch_fused(const float* __restrict__ x, const float* __restrict__ y,
             float* __restrict__ out) {
    const int tid  = threadIdx.x;
    const int lane = tid & 31;
    const int wib  = tid >> 5;

    // Warp-private reduction rows (36-float stride: 16B-aligned, conflict-free)
    __shared__ __align__(16) float red[WARPS_PER_BLOCK][17][36];
    // Double-buffered per-batch sums: epilogue(k) overlaps compute(k+1).
    __shared__ __align__(16) float bsum[2][WARPS_PER_BLOCK][20];

    float loss_acc = 0.0f;   // meaningful on lanes 0..7 of warp 0
    int buf = 0;

    for (int g = blockIdx.x; g < NGROUPS; g += GRID_P, buf ^= 1) {
        // group g = 8 batches; warp wib owns batch g*8+wib.
        const float4* xb = reinterpret_cast<const float4*>(x)
                         + (size_t)g * 768 + wib * 96;
        const float4* yb = reinterpret_cast<const float4*>(y)
                         + (size_t)g * 768 + wib * 96;

        float4 a0 = xb[3 * lane + 0];
        float4 a1 = xb[3 * lane + 1];
        float4 a2 = xb[3 * lane + 2];
        float4 b0 = yb[3 * lane + 0];
        float4 b1 = yb[3 * lane + 1];
        float4 b2 = yb[3 * lane + 2];

        float px[4][3] = {{a0.x, a0.y, a0.z}, {a0.w, a1.x, a1.y},
                          {a1.z, a1.w, a2.x}, {a2.y, a2.z, a2.w}};
        float py[4][3] = {{b0.x, b0.y, b0.z}, {b0.w, b1.x, b1.y},
                          {b1.z, b1.w, b2.x}, {b2.y, b2.z, b2.w}};

        // acc: [0..2]=sx, [3..5]=sy, [6]=sxx, [7]=syy, [8..16]=C row-major
        float acc[17];
#pragma unroll
        for (int i = 0; i < 17; i++) acc[i] = 0.0f;

#pragma unroll
        for (int p = 0; p < 4; p++) {
#pragma unroll
            for (int j = 0; j < 3; j++) {
                acc[j]     += px[p][j];
                acc[3 + j] += py[p][j];
                acc[6]     += px[p][j] * px[p][j];
                acc[7]     += py[p][j] * py[p][j];
            }
#pragma unroll
            for (int j = 0; j < 3; j++)
#pragma unroll
                for (int k = 0; k < 3; k++)
                    acc[8 + 3 * j + k] += px[p][j] * py[p][k];
        }

#pragma unroll
        for (int j = 0; j < 17; j++)
            red[wib][j][lane] = acc[j];      // warp-private: no block hazard
        __syncwarp();

        if (lane < 17) {
            const float4* row = reinterpret_cast<const float4*>(&red[wib][lane][0]);
            float4 v0 = row[0], v1 = row[1], v2 = row[2], v3 = row[3];
            float4 v4 = row[4], v5 = row[5], v6 = row[6], v7 = row[7];
            float s = (((v0.x + v0.y) + (v0.z + v0.w)) + ((v1.x + v1.y) + (v1.z + v1.w)))
                    + (((v2.x + v2.y) + (v2.z + v2.w)) + ((v3.x + v3.y) + (v3.z + v3.w)))
                    + (((v4.x + v4.y) + (v4.z + v4.w)) + ((v5.x + v5.y) + (v5.z + v5.w)))
                    + (((v6.x + v6.y) + (v6.z + v6.w)) + ((v7.x + v7.y) + (v7.z + v7.w)));
            bsum[buf][wib][lane] = s;
        }

        // One barrier per iteration: all warps' bsum[buf] visible to warp 0.
        // Warp 0 epilogues bsum[buf] while others run the next iteration
        // (they write bsum[buf^1] next — no conflict; they rewrite bsum[buf]
        // only after the NEXT barrier, by which warp 0 has long finished).
        __syncthreads();

        if (tid < 8) {
            const int b = tid;
            const float4* bp = reinterpret_cast<const float4*>(&bsum[buf][b][0]);
            float4 q0 = bp[0], q1 = bp[1], q2 = bp[2], q3 = bp[3];
            float c22 = bsum[buf][b][16];

            float sx0 = q0.x, sx1 = q0.y, sx2 = q0.z;
            float sy0 = q0.w, sy1 = q1.x, sy2 = q1.y;
            float sxx = q1.z, syy = q1.w;
            float C00 = q2.x, C01 = q2.y, C02 = q2.z;
            float C10 = q2.w, C11 = q3.x, C12 = q3.y;
            float C20 = q3.z, C21 = q3.w, C22 = c22;

            const float invN = 1.0f / (float)NPTS;

            float cc00 = C00 - sx0 * sy0 * invN;
            float cc01 = C01 - sx0 * sy1 * invN;
            float cc02 = C02 - sx0 * sy2 * invN;
            float cc10 = C10 - sx1 * sy0 * invN;
            float cc11 = C11 - sx1 * sy1 * invN;
            float cc12 = C12 - sx1 * sy2 * invN;
            float cc20 = C20 - sx2 * sy0 * invN;
            float cc21 = C21 - sx2 * sy1 * invN;
            float cc22 = C22 - sx2 * sy2 * invN;

            float ax = sxx - (sx0 * sx0 + sx1 * sx1 + sx2 * sx2) * invN;
            float ay = syy - (sy0 * sy0 + sy1 * sy1 + sy2 * sy2) * invN;

            float m00 = cc00 * cc00 + cc10 * cc10 + cc20 * cc20;
            float m11 = cc01 * cc01 + cc11 * cc11 + cc21 * cc21;
            float m22 = cc02 * cc02 + cc12 * cc12 + cc22 * cc22;
            float m01 = cc00 * cc01 + cc10 * cc11 + cc20 * cc21;
            float m02 = cc00 * cc02 + cc10 * cc12 + cc20 * cc22;
            float m12 = cc01 * cc02 + cc11 * cc12 + cc21 * cc22;

            float q  = (m00 + m11 + m22) * (1.0f / 3.0f);
            float p1 = m01 * m01 + m02 * m02 + m12 * m12;
            float d0 = m00 - q, d1 = m11 - q, d2 = m22 - q;
            float p2 = d0 * d0 + d1 * d1 + d2 * d2 + 2.0f * p1;
            float p  = sqrtf(fmaxf(p2, 0.0f) * (1.0f / 6.0f));

            float nuclear;
            if (p < 1e-10f) {
                nuclear = 3.0f * sqrtf(fmaxf(q, 0.0f));
            } else {
                float ip  = 1.0f / p;
                float b00 = d0 * ip, b11 = d1 * ip, b22 = d2 * ip;
                float b01 = m01 * ip, b02 = m02 * ip, b12 = m12 * ip;
                float detB = b00 * (b11 * b22 - b12 * b12)
                           - b01 * (b01 * b22 - b12 * b02)
                           + b02 * (b01 * b12 - b11 * b02);
                float r = 0.5f * detB;
                r = fminf(1.0f, fmaxf(-1.0f, r));
                float phi = acosf(r) * (1.0f / 3.0f);
                float e1 = q + 2.0f * p * cosf(phi);
                float e3 = q + 2.0f * p * cosf(phi + 2.09439510239319549f);
                float e2 = 3.0f * q - e1 - e3;
                nuclear = sqrtf(fmaxf(e1, 0.0f))
                        + sqrtf(fmaxf(e2, 0.0f))
                        + sqrtf(fmaxf(e3, 0.0f));
            }

            loss_acc += ax + ay - 2.0f * nuclear;
        }
    }

    // ---- block finalize: one atomic per block ----
    if (tid < 8) {
        float loss = loss_acc;
        loss += __shfl_xor_sync(0xFFu, loss, 4);
        loss += __shfl_xor_sync(0xFFu, loss, 2);
        loss += __shfl_xor_sync(0xFFu, loss, 1);

        if (tid == 0) {
            atomicAdd(&g_accum, (double)loss);

            // Last-block finalize: counter wraps at GRID_P-1, so g_count and
            // g_accum are clean for the next graph replay.
            __threadfence();
            unsigned int prev = atomicInc(&g_count, GRID_P - 1u);
            if (prev == GRID_P - 1u) {
                double total = atomicAdd(&g_accum, 0.0);  // coherent read
                const double scale = 1.0 / ((double)NB * (double)NPTS * 3.0);
                out[0] = (float)(total * scale);
                g_accum = 0.0;                            // reset for replay
            }
        }
    }
}

extern "C" void kernel_launch(void* const* d_in, const int* in_sizes, int n_in,
                              void* d_out, int out_size) {
    const float* x = (const float*)d_in[0];
    const float* y = (const float*)d_in[1];
    float* out = (float*)d_out;

    kabsch_fused<<<GRID_P, THREADS>>>(x, y, out);
}